// round 2
// baseline (speedup 1.0000x reference)
#include <cuda_runtime.h>
#include <cuda_bf16.h>
#include <stdint.h>

#define SLICES 192
#define HW 50176
#define WIDTH 224
#define PIX 196
#define DCH 540
#define KPAD1 544
#define NPAD 576
#define CIP 1088
#define M_TOT 12544
#define INVR2 0.70710678118654752440f
#define SA 24

// ----------------------------- scratch globals -----------------------------
__device__ float g_cA[3][SLICES * HW];
__device__ float g_epix[64 * 30 * PIX];
__device__ __nv_bfloat16 g_h[M_TOT * KPAD1];
__device__ float g_m[64 * DCH * PIX];
__device__ __nv_bfloat16 g_B2p[34 * NPAD * 16];
__device__ __nv_bfloat16 g_Bgp[612 * NPAD * 16];
__device__ __nv_bfloat16 g_gip[64 * 16 * 16 * CIP];

// ----------------------------- SWT cA chain --------------------------------
__global__ void ca_kernel(const float* __restrict__ frames, int level) {
    int idx = blockIdx.x * blockDim.x + threadIdx.x;
    if (idx >= SLICES * HW) return;
    const float* src = (level == 0) ? frames : g_cA[level - 1];
    int slice = idx / HW, p = idx % HW;
    int y = p / WIDTH, x = p - y * WIDTH;
    int d = 1 << level;
    int xd = x + d; if (xd >= WIDTH) xd -= WIDTH;
    int yd = y + d; if (yd >= WIDTH) yd -= WIDTH;
    const float* s = src + slice * HW;
    float l0 = (s[y * WIDTH + x] + s[y * WIDTH + xd]) * INVR2;
    float l1 = (s[yd * WIDTH + x] + s[yd * WIDTH + xd]) * INVR2;
    g_cA[level][idx] = (l0 + l1) * INVR2;
}

// --------------- band compute + exact 99th-pct + 16x16 pool ----------------
__global__ __launch_bounds__(512) void band_kernel(const float* __restrict__ frames) {
    extern __shared__ float sd[];
    __shared__ unsigned hist[258];
    __shared__ float pool[PIX];
    __shared__ float sh_mu;
    __shared__ unsigned sh_pfx, sh_minbits;
    __shared__ int sh_krem;

    int bid = blockIdx.x;
    int slice = bid / 10, band = bid % 10;
    int tid = threadIdx.x, lane = tid & 31;
    int lvl = band / 3;
    const float* par = (band < 3) ? frames + slice * HW : g_cA[lvl - 1] + slice * HW;
    int d = 1 << lvl, type = band % 3;

    for (int i = tid; i < HW; i += 512) {
        float v;
        if (band == 9) v = par[i];
        else {
            int y = i / WIDTH, x = i - y * WIDTH;
            int xd = x + d; if (xd >= WIDTH) xd -= WIDTH;
            int yd = y + d; if (yd >= WIDTH) yd -= WIDTH;
            float p00 = par[y * WIDTH + x],  p01 = par[y * WIDTH + xd];
            float p10 = par[yd * WIDTH + x], p11 = par[yd * WIDTH + xd];
            float a0, a1;
            if (type == 0) { a0 = (p00 + p01) * INVR2; a1 = (p10 + p11) * INVR2; v = (a0 - a1) * INVR2; }
            else {
                a0 = (p00 - p01) * INVR2; a1 = (p10 - p11) * INVR2;
                v = (type == 1) ? (a0 + a1) * INVR2 : (a0 - a1) * INVR2;
            }
        }
        sd[i] = v;
    }
    __syncthreads();

    if (tid < PIX) {
        int py = tid / 14, px = tid - py * 14;
        const float* r = sd + py * 16 * WIDTH + px * 16;
        float s = 0.f;
        for (int iy = 0; iy < 16; iy++) {
            float t = 0.f;
            #pragma unroll
            for (int ix = 0; ix < 16; ix++) t += r[iy * WIDTH + ix];
            s += t;
        }
        pool[tid] = s;
    }
    __syncthreads();

    float mu = 0.f;
    if (band == 9) {
        if (tid == 0) {
            float t = 0.f;
            for (int j = 0; j < PIX; j++) t += pool[j];
            sh_mu = t * (1.f / (float)HW);
        }
        __syncthreads();
        mu = sh_mu;
    }

    // exact radix select: 503rd largest of |x-mu| over 50176 elems
    if (tid == 0) { sh_pfx = 0u; sh_krem = 503; }
    __syncthreads();
    for (int ps = 0; ps < 4; ps++) {
        int shift = 24 - 8 * ps;
        unsigned hmask = (ps == 0) ? 0u : (0xFFFFFFFFu << (32 - 8 * ps));
        for (int j = tid; j < 258; j += 512) hist[j] = 0u;
        __syncthreads();
        unsigned pfx = sh_pfx;
        for (int i = tid; i < HW; i += 512) {
            unsigned key = __float_as_uint(fabsf(sd[i] - mu));
            int bin = ((key & hmask) == pfx) ? (int)((key >> shift) & 255u) : 256;
            unsigned mm = __match_any_sync(0xFFFFFFFFu, bin);
            if (lane == __ffs(mm) - 1) atomicAdd(&hist[bin], (unsigned)__popc(mm));
        }
        __syncthreads();
        if (tid == 0) {
            unsigned k = (unsigned)sh_krem, c = 0; int b = 255;
            for (; b > 0; b--) { unsigned h = hist[b]; if (c + h >= k) break; c += h; }
            sh_pfx = pfx | ((unsigned)b << shift);
            sh_krem = (int)(k - c);
        }
        __syncthreads();
    }
    unsigned vbits = sh_pfx;
    int cnt_gt = 503 - sh_krem;     // count strictly greater than vlo
    float vlo = __uint_as_float(vbits), vhi = vlo;
    if (cnt_gt == 502) {            // 502nd largest = min of those > vlo
        if (tid == 0) sh_minbits = 0xFFFFFFFFu;
        __syncthreads();
        unsigned loc = 0xFFFFFFFFu;
        for (int i = tid; i < HW; i += 512) {
            unsigned key = __float_as_uint(fabsf(sd[i] - mu));
            if (key > vbits && key < loc) loc = key;
        }
        atomicMin(&sh_minbits, loc);
        __syncthreads();
        vhi = __uint_as_float(sh_minbits);
    }
    float sq = vlo + 0.25f * (vhi - vlo);  // rank 0.99*(HW-1) = 49673.25
    float inv = 1.f / ((sq + 1e-4f) * 256.f);
    if (tid < PIX) {
        int n = slice / 3, c = slice % 3;
        g_epix[(n * 30 + band * 3 + c) * PIX + tid] = (pool[tid] - 256.f * mu) * inv;
    }
}

// ---------------- gi buffer prep (t_clip -> padded NHWC bf16) --------------
__global__ void prep_gi(const float* __restrict__ t_clip) {
    int idx = blockIdx.x * blockDim.x + threadIdx.x;
    if (idx >= 64 * 256 * CIP) return;
    int ch = idx % CIP; int r = idx / CIP;
    int x = r & 15; int r2 = r >> 4; int y = r2 & 15; int n = r2 >> 4;
    bool inter = (y >= 1 && y <= 14 && x >= 1 && x <= 14);
    if (inter && ch >= 540 && ch < 1080) return;  // filled by gemm2 epilogue
    float v = 0.f;
    if (inter && ch < 540) v = t_clip[(n * DCH + ch) * PIX + (y - 1) * 14 + (x - 1)];
    g_gip[idx] = __float2bfloat16(v);
}

// ---------------------------- weight packing -------------------------------
__global__ void pack_w2(const float* __restrict__ w2) {
    int idx = blockIdx.x * blockDim.x + threadIdx.x;
    if (idx >= 34 * NPAD * 16) return;
    int j = idx & 15; int n = (idx >> 4) % NPAD; int kc = idx / (16 * NPAD);
    int k = kc * 16 + j;
    float v = (n < DCH && k < DCH) ? w2[n * DCH + k] : 0.f;
    g_B2p[idx] = __float2bfloat16(v);
}
__global__ void pack_wg(const float* __restrict__ wg) {
    int idx = blockIdx.x * blockDim.x + threadIdx.x;
    if (idx >= 612 * NPAD * 16) return;
    int j = idx & 15; int n = (idx >> 4) % NPAD; int kc = idx / (16 * NPAD);
    int k = kc * 16 + j; int tap = k / CIP; int c = k - tap * CIP;
    float v = (n < DCH && c < 1080) ? wg[(n * 1080 + c) * 9 + tap] : 0.f;
    g_Bgp[idx] = __float2bfloat16(v);
}

// ------------------------------ MLP layer 1 --------------------------------
__global__ void layer1_kernel(const float* __restrict__ w1, const float* __restrict__ b1) {
    __shared__ float xs[30];
    int m = blockIdx.x; int tid = threadIdx.x;
    int n_img = m / PIX, pix = m - n_img * PIX;
    if (tid < 30) xs[tid] = g_epix[(n_img * 30 + tid) * PIX + pix];
    __syncthreads();
    float v = 0.f;
    if (tid < DCH) {
        v = b1[tid];
        #pragma unroll
        for (int c = 0; c < 30; c++) v += xs[c] * w1[tid * 30 + c];
        v = fmaxf(v, 0.f);
    }
    g_h[m * KPAD1 + tid] = __float2bfloat16(v);
}

// --------------------------- bf16 mma GEMM ---------------------------------
__device__ __forceinline__ void cp16(void* dst, const void* src) {
    unsigned s = (unsigned)__cvta_generic_to_shared(dst);
    asm volatile("cp.async.cg.shared.global [%0],[%1],16;\n" :: "r"(s), "l"(src));
}

// MODE 0: m = tanh(h @ w2^T + b2)  (also writes m into g_gip)
// MODE 1: out = t_clip + sigmoid(conv + bg) * m   (implicit 3x3 conv GEMM)
template<int MODE>
__global__ __launch_bounds__(128) void mma_kernel(
    const float* __restrict__ bias, const float* __restrict__ t_clip,
    float* __restrict__ out, int ksteps)
{
    __shared__ __nv_bfloat16 As[2][64 * SA];
    __shared__ __nv_bfloat16 Bs[2][64 * SA];
    const __nv_bfloat16* Bp = (MODE == 0) ? g_B2p : g_Bgp;
    int tid = threadIdx.x, lane = tid & 31, w = tid >> 5;
    int wm = w >> 1, wn = w & 1;
    int bn = blockIdx.x, bm = blockIdx.y;
    int lrow = tid >> 1, lhalf = tid & 1;
    int m_glob = bm * 64 + lrow;
    const __nv_bfloat16* Asrc = g_h;  // MODE 0 base
    int arb = 0;
    if (MODE == 0) {
        Asrc = g_h + m_glob * KPAD1 + lhalf * 8;
    } else {
        int n_img = m_glob / PIX, pix = m_glob - n_img * PIX;
        int y = pix / 14, x = pix - 14 * y;
        arb = ((n_img * 16 + y) * 16 + x) * CIP + lhalf * 8;
    }
    const __nv_bfloat16* Bsrc = Bp + (bn * 64 + lrow) * 16 + lhalf * 8;

    float acc[2][4][4];
    #pragma unroll
    for (int a = 0; a < 2; a++)
        #pragma unroll
        for (int b = 0; b < 4; b++)
            #pragma unroll
            for (int c = 0; c < 4; c++) acc[a][b][c] = 0.f;

    auto load = [&](int s, int kc) {
        __nv_bfloat16* ad = &As[s][lrow * SA + lhalf * 8];
        if (MODE == 0) cp16(ad, Asrc + kc * 16);
        else {
            int t9 = kc / 68, cc = (kc - t9 * 68) * 16;
            int ky = t9 / 3, kx = t9 - ky * 3;
            cp16(ad, g_gip + arb + (ky * 16 + kx) * CIP + cc);
        }
        cp16(&Bs[s][lrow * SA + lhalf * 8], Bsrc + kc * (NPAD * 16));
        asm volatile("cp.async.commit_group;\n");
    };

    load(0, 0);
    int s = 0;
    int g = lane >> 2, q = lane & 3;
    for (int kc = 0; kc < ksteps; kc++) {
        if (kc + 1 < ksteps) { load(s ^ 1, kc + 1); asm volatile("cp.async.wait_group 1;\n"); }
        else                 { asm volatile("cp.async.wait_group 0;\n"); }
        __syncthreads();
        uint32_t af[2][4], bf[4][2];
        #pragma unroll
        for (int mi = 0; mi < 2; mi++) {
            const __nv_bfloat16* ap = &As[s][(wm * 32 + mi * 16) * SA];
            af[mi][0] = *(const uint32_t*)(ap + g * SA + 2 * q);
            af[mi][1] = *(const uint32_t*)(ap + (g + 8) * SA + 2 * q);
            af[mi][2] = *(const uint32_t*)(ap + g * SA + 2 * q + 8);
            af[mi][3] = *(const uint32_t*)(ap + (g + 8) * SA + 2 * q + 8);
        }
        #pragma unroll
        for (int ni = 0; ni < 4; ni++) {
            const __nv_bfloat16* bp2 = &Bs[s][(wn * 32 + ni * 8 + g) * SA];
            bf[ni][0] = *(const uint32_t*)(bp2 + 2 * q);
            bf[ni][1] = *(const uint32_t*)(bp2 + 2 * q + 8);
        }
        #pragma unroll
        for (int mi = 0; mi < 2; mi++)
            #pragma unroll
            for (int ni = 0; ni < 4; ni++)
                asm volatile("mma.sync.aligned.m16n8k16.row.col.f32.bf16.bf16.f32 "
                    "{%0,%1,%2,%3},{%4,%5,%6,%7},{%8,%9},{%0,%1,%2,%3};\n"
                    : "+f"(acc[mi][ni][0]), "+f"(acc[mi][ni][1]),
                      "+f"(acc[mi][ni][2]), "+f"(acc[mi][ni][3])
                    : "r"(af[mi][0]), "r"(af[mi][1]), "r"(af[mi][2]), "r"(af[mi][3]),
                      "r"(bf[ni][0]), "r"(bf[ni][1]));
        __syncthreads();
        s ^= 1;
    }

    // epilogue
    #pragma unroll
    for (int rr = 0; rr < 4; rr++) {
        int mi = rr >> 1, hh = rr & 1;
        int r = bm * 64 + wm * 32 + mi * 16 + g + hh * 8;
        int n_img = r / PIX, pix = r - n_img * PIX;
        int y = pix / 14, x = pix - 14 * y;
        int gbase = ((n_img * 16 + y + 1) * 16 + (x + 1)) * CIP + 540;
        #pragma unroll
        for (int ni = 0; ni < 4; ni++) {
            #pragma unroll
            for (int cc = 0; cc < 2; cc++) {
                int n = bn * 64 + wn * 32 + ni * 8 + 2 * q + cc;
                if (n >= DCH) continue;
                float v = acc[mi][ni][hh * 2 + cc] + bias[n];
                int oidx = (n_img * DCH + n) * PIX + pix;
                if (MODE == 0) {
                    v = tanhf(v);
                    g_m[oidx] = v;
                    g_gip[gbase + n] = __float2bfloat16(v);
                } else {
                    float gam = 1.f / (1.f + __expf(-v));
                    out[oidx] = t_clip[oidx] + gam * g_m[oidx];
                }
            }
        }
    }
}

// ------------------------------- launcher ----------------------------------
extern "C" void kernel_launch(void* const* d_in, const int* in_sizes, int n_in,
                              void* d_out, int out_size) {
    const float* frames = (const float*)d_in[0];
    const float* t_clip = (const float*)d_in[1];
    const float* w1 = (const float*)d_in[2];
    const float* b1 = (const float*)d_in[3];
    const float* w2 = (const float*)d_in[4];
    const float* b2 = (const float*)d_in[5];
    const float* wg = (const float*)d_in[6];
    const float* bg = (const float*)d_in[7];
    float* out = (float*)d_out;

    int tot = SLICES * HW;
    for (int l = 0; l < 3; l++) ca_kernel<<<(tot + 255) / 256, 256>>>(frames, l);

    cudaFuncSetAttribute(band_kernel, cudaFuncAttributeMaxDynamicSharedMemorySize, HW * 4);
    band_kernel<<<1920, 512, HW * 4>>>(frames);

    prep_gi<<<(64 * 256 * CIP + 255) / 256, 256>>>(t_clip);
    pack_w2<<<(34 * NPAD * 16 + 255) / 256, 256>>>(w2);
    pack_wg<<<(612 * NPAD * 16 + 255) / 256, 256>>>(wg);
    layer1_kernel<<<M_TOT, 544>>>(w1, b1);

    mma_kernel<0><<<dim3(9, 196), 128>>>(b2, t_clip, out, 34);
    mma_kernel<1><<<dim3(9, 196), 128>>>(bg, t_clip, out, 612);
}

// round 6
// speedup vs baseline: 1.4517x; 1.4517x over previous
#include <cuda_runtime.h>
#include <cuda_bf16.h>
#include <stdint.h>

#define SLICES 192
#define HW 50176
#define WIDTH 224
#define PIX 196
#define DCH 540
#define KPAD1 544
#define NPAD 576
#define CIP 1088
#define M_TOT 12544
#define INVR2 0.70710678118654752440f
#define SA 24
#define CAP 4096

// ----------------------------- scratch globals -----------------------------
__device__ float g_cA[3][SLICES * HW];
__device__ float g_epix[64 * 30 * PIX];
__device__ __nv_bfloat16 g_h[M_TOT * KPAD1];
__device__ float g_m[64 * DCH * PIX];
__device__ __nv_bfloat16 g_B2p[34 * NPAD * 16];
__device__ __nv_bfloat16 g_Bgp[612 * NPAD * 16];
__device__ __nv_bfloat16 g_gip[64 * 16 * 16 * CIP];

// ----------------------------- SWT cA chain --------------------------------
__global__ void ca_kernel(const float* __restrict__ frames, int level) {
    int idx = blockIdx.x * blockDim.x + threadIdx.x;
    if (idx >= SLICES * HW) return;
    const float* src = (level == 0) ? frames : g_cA[level - 1];
    int slice = idx / HW, p = idx % HW;
    int y = p / WIDTH, x = p - y * WIDTH;
    int d = 1 << level;
    int xd = x + d; if (xd >= WIDTH) xd -= WIDTH;
    int yd = y + d; if (yd >= WIDTH) yd -= WIDTH;
    const float* s = src + slice * HW;
    float l0 = (s[y * WIDTH + x] + s[y * WIDTH + xd]) * INVR2;
    float l1 = (s[yd * WIDTH + x] + s[yd * WIDTH + xd]) * INVR2;
    g_cA[level][idx] = (l0 + l1) * INVR2;
}

// --------------- band compute + exact 99th-pct + 16x16 pool ----------------
__global__ __launch_bounds__(1024) void band_kernel(const float* __restrict__ frames) {
    extern __shared__ float sd[];
    __shared__ unsigned hist[16][256];   // pass-1 per-warp-pair hists; reused as compact buffer
    __shared__ unsigned red[256];
    __shared__ float pool[PIX];
    __shared__ float sh_mu;
    __shared__ unsigned sh_cnt, sh_pfx, sh_min;
    __shared__ int sh_above, sh_bin, sh_r, sh_krem;

    int bid = blockIdx.x;
    int slice = bid / 10, band = bid % 10;
    int tid = threadIdx.x, lane = tid & 31;
    int wp = tid >> 6;  // warp-pair 0..15
    int lvl = band / 3;
    const float* par = (band < 3) ? frames + slice * HW : g_cA[lvl - 1] + slice * HW;
    int d = 1 << lvl, type = band % 3;

    unsigned* h16 = &hist[0][0];
    for (int j = tid; j < 4096; j += 1024) h16[j] = 0u;
    __syncthreads();

    // scan1: compute band into smem; fused top-8-bit histogram (mu=0 bands)
    for (int i = tid; i < HW; i += 1024) {
        float v;
        if (band == 9) v = par[i];
        else {
            int y = i / WIDTH, x = i - y * WIDTH;
            int xd = x + d; if (xd >= WIDTH) xd -= WIDTH;
            int yd = y + d; if (yd >= WIDTH) yd -= WIDTH;
            float p00 = par[y * WIDTH + x],  p01 = par[y * WIDTH + xd];
            float p10 = par[yd * WIDTH + x], p11 = par[yd * WIDTH + xd];
            float a0, a1;
            if (type == 0) { a0 = (p00 + p01) * INVR2; a1 = (p10 + p11) * INVR2; v = (a0 - a1) * INVR2; }
            else {
                a0 = (p00 - p01) * INVR2; a1 = (p10 - p11) * INVR2;
                v = (type == 1) ? (a0 + a1) * INVR2 : (a0 - a1) * INVR2;
            }
        }
        sd[i] = v;
        if (band < 9) {
            unsigned key = __float_as_uint(fabsf(v));
            atomicAdd(&hist[wp][key >> 24], 1u);
        }
    }
    __syncthreads();

    // pool: 784 threads, 4 per output pixel
    if (tid < 784) {
        int slot = tid >> 2, sub = tid & 3;
        int py = slot / 14, px = slot - py * 14;
        const float* r = sd + (py * 16 + sub * 4) * WIDTH + px * 16;
        float s = 0.f;
        for (int iy = 0; iy < 4; iy++) {
            float t = 0.f;
            #pragma unroll
            for (int ix = 0; ix < 16; ix++) t += r[iy * WIDTH + ix];
            s += t;
        }
        unsigned pm = __activemask();
        s += __shfl_xor_sync(pm, s, 1);
        s += __shfl_xor_sync(pm, s, 2);
        if (sub == 0) pool[slot] = s;
    }
    __syncthreads();

    float mu = 0.f;
    if (band == 9) {
        if (tid < 32) {
            float t = 0.f;
            for (int j = lane; j < PIX; j += 32) t += pool[j];
            #pragma unroll
            for (int o = 16; o > 0; o >>= 1) t += __shfl_xor_sync(0xFFFFFFFFu, t, o);
            if (lane == 0) sh_mu = t * (1.f / (float)HW);
        }
        __syncthreads();
        mu = sh_mu;
        for (int i = tid; i < HW; i += 1024) {
            unsigned key = __float_as_uint(fabsf(sd[i] - mu));
            atomicAdd(&hist[wp][key >> 24], 1u);
        }
        __syncthreads();
    }

    // reduce 16 hists; find threshold bin for rank 503-from-top
    if (tid < 256) {
        unsigned s = 0;
        #pragma unroll
        for (int j = 0; j < 16; j++) s += hist[j][tid];
        red[tid] = s;
    }
    __syncthreads();
    if (tid == 0) {
        unsigned k = 503u, c = 0; int b = 255;
        for (; b > 0; b--) { unsigned h = red[b]; if (c + h >= k) break; c += h; }
        sh_bin = b; sh_above = (int)c; sh_r = (int)(k - c); sh_cnt = 0u;
    }
    __syncthreads();
    int b = sh_bin, r = sh_r, above = sh_above;
    unsigned* buf = &hist[0][0];  // reuse 16KB as compact buffer

    // compact: gather all elements whose top-8 bits == b
    for (int i = tid; i < HW; i += 1024) {
        unsigned key = __float_as_uint(fabsf(sd[i] - mu));
        if ((key >> 24) == (unsigned)b) {
            unsigned p = atomicAdd(&sh_cnt, 1u);
            if (p < CAP) buf[p] = key;
        }
    }
    __syncthreads();
    unsigned cnt = sh_cnt;

    if (tid == 0) { sh_pfx = (unsigned)b << 24; sh_krem = r; }
    __syncthreads();

    if (cnt <= CAP) {
        // 3x 8-bit radix select over the small buffer
        for (int ps = 0; ps < 3; ps++) {
            int shift = 16 - 8 * ps;
            unsigned hmask = 0xFFFFFFFFu << (shift + 8);
            if (tid < 256) red[tid] = 0u;
            __syncthreads();
            unsigned pfx = sh_pfx;
            for (unsigned i = tid; i < cnt; i += 1024) {
                unsigned key = buf[i];
                if ((key & hmask) == pfx) atomicAdd(&red[(key >> shift) & 255u], 1u);
            }
            __syncthreads();
            if (tid == 0) {
                unsigned k = (unsigned)sh_krem, c = 0; int b8 = 255;
                for (; b8 > 0; b8--) { unsigned h = red[b8]; if (c + h >= k) break; c += h; }
                sh_pfx = pfx | ((unsigned)b8 << shift);
                sh_krem = (int)(k - c);
            }
            __syncthreads();
        }
    } else {
        // fallback (never expected): radix select over full smem band
        for (int ps = 0; ps < 3; ps++) {
            int shift = 16 - 8 * ps;
            unsigned hmask = 0xFFFFFFFFu << (shift + 8);
            if (tid < 256) red[tid] = 0u;
            __syncthreads();
            unsigned pfx = sh_pfx;
            for (int i = tid; i < HW; i += 1024) {
                unsigned key = __float_as_uint(fabsf(sd[i] - mu));
                if ((key & hmask) == pfx) atomicAdd(&red[(key >> shift) & 255u], 1u);
            }
            __syncthreads();
            if (tid == 0) {
                unsigned k = (unsigned)sh_krem, c = 0; int b8 = 255;
                for (; b8 > 0; b8--) { unsigned h = red[b8]; if (c + h >= k) break; c += h; }
                sh_pfx = pfx | ((unsigned)b8 << shift);
                sh_krem = (int)(k - c);
            }
            __syncthreads();
        }
    }
    unsigned vbits = sh_pfx;
    int cnt_gt = above + (r - sh_krem);  // strictly greater than vlo
    float vlo = __uint_as_float(vbits), vhi = vlo;
    if (cnt_gt == 502) {                 // 502nd largest = min of keys > vlo
        if (tid == 0) sh_min = 0xFFFFFFFFu;
        __syncthreads();
        unsigned loc = 0xFFFFFFFFu;
        if (cnt <= CAP) {
            for (unsigned i = tid; i < cnt; i += 1024) {
                unsigned key = buf[i];
                if (key > vbits && key < loc) loc = key;
            }
        }
        atomicMin(&sh_min, loc);
        __syncthreads();
        if (sh_min == 0xFFFFFFFFu) {   // not in this bin: scan all
            loc = 0xFFFFFFFFu;
            for (int i = tid; i < HW; i += 1024) {
                unsigned key = __float_as_uint(fabsf(sd[i] - mu));
                if (key > vbits && key < loc) loc = key;
            }
            atomicMin(&sh_min, loc);
            __syncthreads();
        }
        vhi = __uint_as_float(sh_min);
    }
    float sq = vlo + 0.25f * (vhi - vlo);   // rank 0.99*(HW-1) = 49673.25
    float inv = 1.f / ((sq + 1e-4f) * 256.f);
    if (tid < PIX) {
        int n = slice / 3, c = slice % 3;
        g_epix[(n * 30 + band * 3 + c) * PIX + tid] = (pool[tid] - 256.f * mu) * inv;
    }
}

// ------------- gi buffer: zero borders/pads + coalesced transpose ----------
__global__ void zero_gi() {
    int idx = blockIdx.x * blockDim.x + threadIdx.x;
    if (idx >= 64 * 256 * CIP) return;
    int ch = idx % CIP; int rr = idx / CIP;
    int x = rr & 15; int y = (rr >> 4) & 15;
    bool inter = (y >= 1 && y <= 14 && x >= 1 && x <= 14);
    if (inter && ch < 1080) return;   // interior real channels written elsewhere
    g_gip[idx] = __float2bfloat16(0.f);
}

__global__ __launch_bounds__(256) void trans_gi(const float* __restrict__ t_clip) {
    __shared__ float sm[16][PIX];
    int n = blockIdx.x, ch0 = blockIdx.y * 16;
    for (int i = threadIdx.x; i < 16 * PIX; i += 256) {
        int c = i / PIX, p = i - c * PIX;
        int ch = ch0 + c;
        sm[c][p] = (ch < DCH) ? t_clip[(n * DCH + ch) * PIX + p] : 0.f;
    }
    __syncthreads();
    for (int i = threadIdx.x; i < PIX * 16; i += 256) {
        int p = i >> 4, c = i & 15;
        int ch = ch0 + c; if (ch >= DCH) continue;
        int y = p / 14, x = p - 14 * y;
        g_gip[((n * 16 + y + 1) * 16 + (x + 1)) * CIP + ch] = __float2bfloat16(sm[c][p]);
    }
}

// ---------------------------- weight packing -------------------------------
__global__ void pack_w2(const float* __restrict__ w2) {
    int idx = blockIdx.x * blockDim.x + threadIdx.x;
    if (idx >= 34 * NPAD * 16) return;
    int j = idx & 15; int n = (idx >> 4) % NPAD; int kc = idx / (16 * NPAD);
    int k = kc * 16 + j;
    float v = (n < DCH && k < DCH) ? w2[n * DCH + k] : 0.f;
    g_B2p[idx] = __float2bfloat16(v);
}

__global__ __launch_bounds__(256) void pack_wg(const float* __restrict__ wg) {
    __shared__ float sm[9720];   // one output channel's 1080*9 weights
    int n = blockIdx.x;
    if (n < DCH)
        for (int i = threadIdx.x; i < 9720; i += 256) sm[i] = wg[n * 9720 + i];
    __syncthreads();
    for (int i = threadIdx.x; i < 612 * 16; i += 256) {
        int kc = i >> 4, j = i & 15;
        int k = kc * 16 + j;
        int tap = k / CIP, c = k - tap * CIP;
        float v = (n < DCH && c < 1080) ? sm[c * 9 + tap] : 0.f;
        g_Bgp[kc * (NPAD * 16) + n * 16 + j] = __float2bfloat16(v);
    }
}

// ------------------------------ MLP layer 1 --------------------------------
__global__ void layer1_kernel(const float* __restrict__ w1, const float* __restrict__ b1) {
    __shared__ float xs[30];
    int m = blockIdx.x; int tid = threadIdx.x;
    int n_img = m / PIX, pix = m - n_img * PIX;
    if (tid < 30) xs[tid] = g_epix[(n_img * 30 + tid) * PIX + pix];
    __syncthreads();
    float v = 0.f;
    if (tid < DCH) {
        v = b1[tid];
        #pragma unroll
        for (int c = 0; c < 30; c++) v += xs[c] * w1[tid * 30 + c];
        v = fmaxf(v, 0.f);
    }
    g_h[m * KPAD1 + tid] = __float2bfloat16(v);
}

// --------------------------- bf16 mma GEMM ---------------------------------
__device__ __forceinline__ void cp16(void* dst, const void* src) {
    unsigned s = (unsigned)__cvta_generic_to_shared(dst);
    asm volatile("cp.async.cg.shared.global [%0],[%1],16;\n" :: "r"(s), "l"(src));
}

// MODE 0: m = tanh(h @ w2^T + b2)  (also writes m into g_gip)
// MODE 1: out = t_clip + sigmoid(conv + bg) * m   (implicit 3x3 conv GEMM)
template<int MODE>
__global__ __launch_bounds__(256) void mma_kernel(
    const float* __restrict__ bias, const float* __restrict__ t_clip,
    float* __restrict__ out, int ksteps)
{
    __shared__ __align__(16) __nv_bfloat16 As[3][128 * SA];
    __shared__ __align__(16) __nv_bfloat16 Bs[3][64 * SA];
    const __nv_bfloat16* Bp = (MODE == 0) ? g_B2p : g_Bgp;
    int tid = threadIdx.x, lane = tid & 31, w = tid >> 5;
    int wm = w >> 1, wn = w & 1;
    int bn = blockIdx.x, bm = blockIdx.y;
    int arow = tid >> 1, ahalf = tid & 1;
    int m_glob = bm * 128 + arow;
    const __nv_bfloat16* Asrc = g_h;
    int arb = 0;
    if (MODE == 0) {
        Asrc = g_h + m_glob * KPAD1 + ahalf * 8;
    } else {
        int n_img = m_glob / PIX, pix = m_glob - n_img * PIX;
        int y = pix / 14, x = pix - 14 * y;
        arb = ((n_img * 16 + y) * 16 + x) * CIP + ahalf * 8;
    }
    int brow = (tid & 127) >> 1, bhalf = tid & 1;
    const __nv_bfloat16* Bsrc = Bp + (bn * 64 + brow) * 16 + bhalf * 8;

    float acc[2][4][4];
    #pragma unroll
    for (int a = 0; a < 2; a++)
        #pragma unroll
        for (int bq = 0; bq < 4; bq++)
            #pragma unroll
            for (int c = 0; c < 4; c++) acc[a][bq][c] = 0.f;

    auto load = [&](int s, int kc) {
        __nv_bfloat16* ad = &As[s][arow * SA + ahalf * 8];
        if (MODE == 0) cp16(ad, Asrc + kc * 16);
        else {
            int t9 = kc / 68, cc = (kc - t9 * 68) * 16;
            int ky = t9 / 3, kx = t9 - ky * 3;
            cp16(ad, g_gip + arb + (ky * 16 + kx) * CIP + cc);
        }
        if (tid < 128) cp16(&Bs[s][brow * SA + bhalf * 8], Bsrc + kc * (NPAD * 16));
        asm volatile("cp.async.commit_group;\n");
    };

    load(0, 0);
    load(1, 1);
    int g = lane >> 2, q = lane & 3;
    for (int kc = 0; kc < ksteps; kc++) {
        int s = kc % 3;
        if (kc + 2 < ksteps) { load((kc + 2) % 3, kc + 2); asm volatile("cp.async.wait_group 2;\n"); }
        else if (kc + 1 < ksteps) { asm volatile("cp.async.wait_group 1;\n"); }
        else { asm volatile("cp.async.wait_group 0;\n"); }
        __syncthreads();
        uint32_t af[2][4], bf[4][2];
        #pragma unroll
        for (int mi = 0; mi < 2; mi++) {
            const __nv_bfloat16* ap = &As[s][(wm * 32 + mi * 16) * SA];
            af[mi][0] = *(const uint32_t*)(ap + g * SA + 2 * q);
            af[mi][1] = *(const uint32_t*)(ap + (g + 8) * SA + 2 * q);
            af[mi][2] = *(const uint32_t*)(ap + g * SA + 2 * q + 8);
            af[mi][3] = *(const uint32_t*)(ap + (g + 8) * SA + 2 * q + 8);
        }
        #pragma unroll
        for (int ni = 0; ni < 4; ni++) {
            const __nv_bfloat16* bp2 = &Bs[s][(wn * 32 + ni * 8 + g) * SA];
            bf[ni][0] = *(const uint32_t*)(bp2 + 2 * q);
            bf[ni][1] = *(const uint32_t*)(bp2 + 2 * q + 8);
        }
        #pragma unroll
        for (int mi = 0; mi < 2; mi++)
            #pragma unroll
            for (int ni = 0; ni < 4; ni++)
                asm volatile("mma.sync.aligned.m16n8k16.row.col.f32.bf16.bf16.f32 "
                    "{%0,%1,%2,%3},{%4,%5,%6,%7},{%8,%9},{%0,%1,%2,%3};\n"
                    : "+f"(acc[mi][ni][0]), "+f"(acc[mi][ni][1]),
                      "+f"(acc[mi][ni][2]), "+f"(acc[mi][ni][3])
                    : "r"(af[mi][0]), "r"(af[mi][1]), "r"(af[mi][2]), "r"(af[mi][3]),
                      "r"(bf[ni][0]), "r"(bf[ni][1]));
        __syncthreads();
    }

    // epilogue
    #pragma unroll
    for (int rr = 0; rr < 4; rr++) {
        int mi = rr >> 1, hh = rr & 1;
        int r = bm * 128 + wm * 32 + mi * 16 + g + hh * 8;
        int n_img = r / PIX, pix = r - n_img * PIX;
        int y = pix / 14, x = pix - 14 * y;
        int gbase = ((n_img * 16 + y + 1) * 16 + (x + 1)) * CIP + 540;
        #pragma unroll
        for (int ni = 0; ni < 4; ni++) {
            #pragma unroll
            for (int cc = 0; cc < 2; cc++) {
                int n = bn * 64 + wn * 32 + ni * 8 + 2 * q + cc;
                if (n >= DCH) continue;
                float v = acc[mi][ni][hh * 2 + cc] + bias[n];
                int oidx = (n_img * DCH + n) * PIX + pix;
                if (MODE == 0) {
                    v = tanhf(v);
                    g_m[oidx] = v;
                    g_gip[gbase + n] = __float2bfloat16(v);
                } else {
                    float gam = 1.f / (1.f + __expf(-v));
                    out[oidx] = t_clip[oidx] + gam * g_m[oidx];
                }
            }
        }
    }
}

// ------------------------------- launcher ----------------------------------
extern "C" void kernel_launch(void* const* d_in, const int* in_sizes, int n_in,
                              void* d_out, int out_size) {
    const float* frames = (const float*)d_in[0];
    const float* t_clip = (const float*)d_in[1];
    const float* w1 = (const float*)d_in[2];
    const float* b1 = (const float*)d_in[3];
    const float* w2 = (const float*)d_in[4];
    const float* b2 = (const float*)d_in[5];
    const float* wg = (const float*)d_in[6];
    const float* bg = (const float*)d_in[7];
    float* out = (float*)d_out;

    int tot = SLICES * HW;
    for (int l = 0; l < 3; l++) ca_kernel<<<(tot + 255) / 256, 256>>>(frames, l);

    cudaFuncSetAttribute(band_kernel, cudaFuncAttributeMaxDynamicSharedMemorySize, HW * 4);
    band_kernel<<<1920, 1024, HW * 4>>>(frames);

    zero_gi<<<(64 * 256 * CIP + 255) / 256, 256>>>();
    trans_gi<<<dim3(64, 34), 256>>>(t_clip);
    pack_w2<<<(34 * NPAD * 16 + 255) / 256, 256>>>(w2);
    pack_wg<<<NPAD, 256>>>(wg);
    layer1_kernel<<<M_TOT, 544>>>(w1, b1);

    mma_kernel<0><<<dim3(9, 98), 256>>>(b2, t_clip, out, 34);
    mma_kernel<1><<<dim3(9, 98), 256>>>(bg, t_clip, out, 612);
}

// round 13
// speedup vs baseline: 1.7972x; 1.2380x over previous
#include <cuda_runtime.h>
#include <cuda_bf16.h>
#include <stdint.h>

#define SLICES 192
#define HW 50176
#define WIDTH 224
#define NCHK 12544      // HW/4
#define CPR 56          // float4 chunks per row
#define PIX 196
#define DCH 540
#define KPAD1 544
#define NPAD 576
#define CIP 1088
#define M_TOT 12544
#define INVR2 0.70710678118654752440f
#define SB 40           // smem K stride (32 + 8 pad) for mma tiles
#define CAP 4096

// ----------------------------- scratch globals -----------------------------
__device__ float g_cA[3][SLICES * HW];
__device__ float g_epix[64 * 30 * PIX];
__device__ __nv_bfloat16 g_h[M_TOT * KPAD1];
__device__ float g_m[64 * DCH * PIX];
__device__ __nv_bfloat16 g_B2p[17 * NPAD * 32];
__device__ __nv_bfloat16 g_Bgp[306 * NPAD * 32];
__device__ __nv_bfloat16 g_gip[64 * 16 * 16 * CIP];

// ----------------------------- SWT cA chain --------------------------------
__global__ void ca_kernel(const float* __restrict__ frames, int level) {
    int idx = blockIdx.x * blockDim.x + threadIdx.x;
    if (idx >= SLICES * HW) return;
    const float* src = (level == 0) ? frames : g_cA[level - 1];
    int slice = idx / HW, p = idx % HW;
    int y = p / WIDTH, x = p - y * WIDTH;
    int d = 1 << level;
    int xd = x + d; if (xd >= WIDTH) xd -= WIDTH;
    int yd = y + d; if (yd >= WIDTH) yd -= WIDTH;
    const float* s = src + slice * HW;
    float l0 = (s[y * WIDTH + x] + s[y * WIDTH + xd]) * INVR2;
    float l1 = (s[yd * WIDTH + x] + s[yd * WIDTH + xd]) * INVR2;
    g_cA[level][idx] = (l0 + l1) * INVR2;
}

// --------------- band compute + exact 99th-pct + 16x16 pool ----------------
__global__ __launch_bounds__(1024) void band_kernel(const float* __restrict__ frames) {
    extern __shared__ float sd[];
    __shared__ unsigned hist[16][256];
    __shared__ unsigned red[256];
    __shared__ float pool[PIX];
    __shared__ float sh_mu;
    __shared__ unsigned sh_cnt, sh_pfx, sh_min;
    __shared__ int sh_above, sh_bin, sh_r, sh_krem;

    int bid = blockIdx.x;
    int slice = bid / 10, band = bid % 10;
    int tid = threadIdx.x, lane = tid & 31;
    int wp = tid >> 6;
    int lvl = band / 3;
    const float* par = (band < 3) ? frames + slice * HW : g_cA[lvl - 1] + slice * HW;
    int d = 1 << lvl, type = band % 3;

    unsigned* h16 = &hist[0][0];
    for (int j = tid; j < 4096; j += 1024) h16[j] = 0u;
    __syncthreads();

    float mu = 0.f;
    unsigned* buf = &hist[0][0];   // 16KB reuse as candidate buffer

    if (band < 9) {
        float s1 = (type == 0) ? 1.f : -1.f;
        float s2 = (type == 1) ? 1.f : -1.f;
        // vectorized scan1: compute band + fused top-8-bit histogram
        for (int c = tid; c < NCHK; c += 1024) {
            int y = c / CPR, cx = c - y * CPR;
            int cxn = (cx + 1 == CPR) ? 0 : cx + 1;
            int yd = y + d; if (yd >= WIDTH) yd -= WIDTH;
            const float4* r0 = (const float4*)(par + y * WIDTH);
            const float4* r1 = (const float4*)(par + yd * WIDTH);
            float4 a0 = r0[cx], b0 = r0[cxn];
            float4 a1 = r1[cx], b1 = r1[cxn];
            float4 t0, t1;
            if (d == 1) {
                t0 = make_float4(a0.y, a0.z, a0.w, b0.x);
                t1 = make_float4(a1.y, a1.z, a1.w, b1.x);
            } else if (d == 2) {
                t0 = make_float4(a0.z, a0.w, b0.x, b0.y);
                t1 = make_float4(a1.z, a1.w, b1.x, b1.y);
            } else {
                t0 = b0; t1 = b1;
            }
            float4 v;
            v.x = (a0.x + s1 * t0.x + s2 * (a1.x + s1 * t1.x)) * 0.5f;
            v.y = (a0.y + s1 * t0.y + s2 * (a1.y + s1 * t1.y)) * 0.5f;
            v.z = (a0.z + s1 * t0.z + s2 * (a1.z + s1 * t1.z)) * 0.5f;
            v.w = (a0.w + s1 * t0.w + s2 * (a1.w + s1 * t1.w)) * 0.5f;
            ((float4*)sd)[c] = v;
            atomicAdd(&hist[wp][__float_as_uint(fabsf(v.x)) >> 24], 1u);
            atomicAdd(&hist[wp][__float_as_uint(fabsf(v.y)) >> 24], 1u);
            atomicAdd(&hist[wp][__float_as_uint(fabsf(v.z)) >> 24], 1u);
            atomicAdd(&hist[wp][__float_as_uint(fabsf(v.w)) >> 24], 1u);
        }
        __syncthreads();
        // reduce hists, find threshold bin
        if (tid < 256) {
            unsigned s = 0;
            #pragma unroll
            for (int j = 0; j < 16; j++) s += hist[j][tid];
            red[tid] = s;
        }
        __syncthreads();
        if (tid == 0) {
            unsigned k = 503u, c = 0; int b = 255;
            for (; b > 0; b--) { unsigned h = red[b]; if (c + h >= k) break; c += h; }
            sh_bin = b; sh_above = (int)c; sh_r = (int)(k - c); sh_cnt = 0u;
        }
        __syncthreads();
        unsigned bb = (unsigned)sh_bin;
        // fused pool + compact (784 threads cover all 50176 elems)
        if (tid < 784) {
            int slot = tid >> 2, sub = tid & 3;
            int py = slot / 14, px = slot - py * 14;
            float s = 0.f;
            for (int iy = 0; iy < 4; iy++) {
                const float4* r = (const float4*)(sd + (py * 16 + sub * 4 + iy) * WIDTH + px * 16);
                #pragma unroll
                for (int j = 0; j < 4; j++) {
                    float4 v = r[j];
                    s += v.x + v.y + v.z + v.w;
                    unsigned kx_ = __float_as_uint(fabsf(v.x));
                    unsigned ky_ = __float_as_uint(fabsf(v.y));
                    unsigned kz_ = __float_as_uint(fabsf(v.z));
                    unsigned kw_ = __float_as_uint(fabsf(v.w));
                    if ((kx_ >> 24) == bb) { unsigned p = atomicAdd(&sh_cnt, 1u); if (p < CAP) buf[p] = kx_; }
                    if ((ky_ >> 24) == bb) { unsigned p = atomicAdd(&sh_cnt, 1u); if (p < CAP) buf[p] = ky_; }
                    if ((kz_ >> 24) == bb) { unsigned p = atomicAdd(&sh_cnt, 1u); if (p < CAP) buf[p] = kz_; }
                    if ((kw_ >> 24) == bb) { unsigned p = atomicAdd(&sh_cnt, 1u); if (p < CAP) buf[p] = kw_; }
                }
            }
            unsigned pm = __activemask();
            s += __shfl_xor_sync(pm, s, 1);
            s += __shfl_xor_sync(pm, s, 2);
            if (sub == 0) pool[slot] = s;
        }
        __syncthreads();
    } else {
        // LL band: copy, pool, mu, hist, compact (scalar; only 192 blocks)
        for (int c = tid; c < NCHK; c += 1024)
            ((float4*)sd)[c] = ((const float4*)par)[c];
        __syncthreads();
        if (tid < 784) {
            int slot = tid >> 2, sub = tid & 3;
            int py = slot / 14, px = slot - py * 14;
            float s = 0.f;
            for (int iy = 0; iy < 4; iy++) {
                const float4* r = (const float4*)(sd + (py * 16 + sub * 4 + iy) * WIDTH + px * 16);
                #pragma unroll
                for (int j = 0; j < 4; j++) {
                    float4 v = r[j];
                    s += v.x + v.y + v.z + v.w;
                }
            }
            unsigned pm = __activemask();
            s += __shfl_xor_sync(pm, s, 1);
            s += __shfl_xor_sync(pm, s, 2);
            if (sub == 0) pool[slot] = s;
        }
        __syncthreads();
        if (tid < 32) {
            float t = 0.f;
            for (int j = lane; j < PIX; j += 32) t += pool[j];
            #pragma unroll
            for (int o = 16; o > 0; o >>= 1) t += __shfl_xor_sync(0xFFFFFFFFu, t, o);
            if (lane == 0) sh_mu = t * (1.f / (float)HW);
        }
        __syncthreads();
        mu = sh_mu;
        for (int i = tid; i < HW; i += 1024) {
            unsigned key = __float_as_uint(fabsf(sd[i] - mu));
            atomicAdd(&hist[wp][key >> 24], 1u);
        }
        __syncthreads();
        if (tid < 256) {
            unsigned s = 0;
            #pragma unroll
            for (int j = 0; j < 16; j++) s += hist[j][tid];
            red[tid] = s;
        }
        __syncthreads();
        if (tid == 0) {
            unsigned k = 503u, c = 0; int b = 255;
            for (; b > 0; b--) { unsigned h = red[b]; if (c + h >= k) break; c += h; }
            sh_bin = b; sh_above = (int)c; sh_r = (int)(k - c); sh_cnt = 0u;
        }
        __syncthreads();
        unsigned bb = (unsigned)sh_bin;
        for (int i = tid; i < HW; i += 1024) {
            unsigned key = __float_as_uint(fabsf(sd[i] - mu));
            if ((key >> 24) == bb) {
                unsigned p = atomicAdd(&sh_cnt, 1u);
                if (p < CAP) buf[p] = key;
            }
        }
        __syncthreads();
    }

    int b = sh_bin, r = sh_r, above = sh_above;
    unsigned cnt = sh_cnt;
    if (tid == 0) { sh_pfx = (unsigned)b << 24; sh_krem = r; }
    __syncthreads();

    if (cnt <= CAP) {
        for (int ps = 0; ps < 3; ps++) {
            int shift = 16 - 8 * ps;
            unsigned hmask = 0xFFFFFFFFu << (shift + 8);
            if (tid < 256) red[tid] = 0u;
            __syncthreads();
            unsigned pfx = sh_pfx;
            for (unsigned i = tid; i < cnt; i += 1024) {
                unsigned key = buf[i];
                if ((key & hmask) == pfx) atomicAdd(&red[(key >> shift) & 255u], 1u);
            }
            __syncthreads();
            if (tid == 0) {
                unsigned k = (unsigned)sh_krem, c = 0; int b8 = 255;
                for (; b8 > 0; b8--) { unsigned h = red[b8]; if (c + h >= k) break; c += h; }
                sh_pfx = pfx | ((unsigned)b8 << shift);
                sh_krem = (int)(k - c);
            }
            __syncthreads();
        }
    } else {
        for (int ps = 0; ps < 3; ps++) {
            int shift = 16 - 8 * ps;
            unsigned hmask = 0xFFFFFFFFu << (shift + 8);
            if (tid < 256) red[tid] = 0u;
            __syncthreads();
            unsigned pfx = sh_pfx;
            for (int i = tid; i < HW; i += 1024) {
                unsigned key = __float_as_uint(fabsf(sd[i] - mu));
                if ((key & hmask) == pfx) atomicAdd(&red[(key >> shift) & 255u], 1u);
            }
            __syncthreads();
            if (tid == 0) {
                unsigned k = (unsigned)sh_krem, c = 0; int b8 = 255;
                for (; b8 > 0; b8--) { unsigned h = red[b8]; if (c + h >= k) break; c += h; }
                sh_pfx = pfx | ((unsigned)b8 << shift);
                sh_krem = (int)(k - c);
            }
            __syncthreads();
        }
    }
    unsigned vbits = sh_pfx;
    int cnt_gt = above + (r - sh_krem);
    float vlo = __uint_as_float(vbits), vhi = vlo;
    if (cnt_gt == 502) {
        if (tid == 0) sh_min = 0xFFFFFFFFu;
        __syncthreads();
        unsigned loc = 0xFFFFFFFFu;
        if (cnt <= CAP) {
            for (unsigned i = tid; i < cnt; i += 1024) {
                unsigned key = buf[i];
                if (key > vbits && key < loc) loc = key;
            }
        }
        atomicMin(&sh_min, loc);
        __syncthreads();
        if (sh_min == 0xFFFFFFFFu) {
            loc = 0xFFFFFFFFu;
            for (int i = tid; i < HW; i += 1024) {
                unsigned key = __float_as_uint(fabsf(sd[i] - mu));
                if (key > vbits && key < loc) loc = key;
            }
            atomicMin(&sh_min, loc);
            __syncthreads();
        }
        vhi = __uint_as_float(sh_min);
    }
    float sq = vlo + 0.25f * (vhi - vlo);   // rank 0.99*(HW-1) = 49673.25
    float inv = 1.f / ((sq + 1e-4f) * 256.f);
    if (tid < PIX) {
        int n = slice / 3, c = slice % 3;
        g_epix[(n * 30 + band * 3 + c) * PIX + tid] = (pool[tid] - 256.f * mu) * inv;
    }
}

// ------------- gi buffer: zero borders/pads + coalesced transpose ----------
__global__ void zero_gi() {
    int idx = blockIdx.x * blockDim.x + threadIdx.x;
    if (idx >= 64 * 256 * CIP) return;
    int ch = idx % CIP; int rr = idx / CIP;
    int x = rr & 15; int y = (rr >> 4) & 15;
    bool inter = (y >= 1 && y <= 14 && x >= 1 && x <= 14);
    if (inter && ch < 1080) return;
    g_gip[idx] = __float2bfloat16(0.f);
}

__global__ __launch_bounds__(256) void trans_gi(const float* __restrict__ t_clip) {
    __shared__ float sm[16][PIX];
    int n = blockIdx.x, ch0 = blockIdx.y * 16;
    for (int i = threadIdx.x; i < 16 * PIX; i += 256) {
        int c = i / PIX, p = i - c * PIX;
        int ch = ch0 + c;
        sm[c][p] = (ch < DCH) ? t_clip[(n * DCH + ch) * PIX + p] : 0.f;
    }
    __syncthreads();
    for (int i = threadIdx.x; i < PIX * 16; i += 256) {
        int p = i >> 4, c = i & 15;
        int ch = ch0 + c; if (ch >= DCH) continue;
        int y = p / 14, x = p - 14 * y;
        g_gip[((n * 16 + y + 1) * 16 + (x + 1)) * CIP + ch] = __float2bfloat16(sm[c][p]);
    }
}

// ---------------------------- weight packing (32-wide K chunks) ------------
__global__ void pack_w2(const float* __restrict__ w2) {
    int idx = blockIdx.x * blockDim.x + threadIdx.x;
    if (idx >= 17 * NPAD * 32) return;
    int j = idx & 31; int n = (idx >> 5) % NPAD; int kc = idx / (32 * NPAD);
    int k = kc * 32 + j;
    float v = (n < DCH && k < DCH) ? w2[n * DCH + k] : 0.f;
    g_B2p[idx] = __float2bfloat16(v);
}

__global__ __launch_bounds__(256) void pack_wg(const float* __restrict__ wg) {
    __shared__ float sm[9720];
    int n = blockIdx.x;
    if (n < DCH)
        for (int i = threadIdx.x; i < 9720; i += 256) sm[i] = wg[n * 9720 + i];
    __syncthreads();
    for (int i = threadIdx.x; i < 306 * 32; i += 256) {
        int kc = i >> 5, j = i & 31;
        int k = kc * 32 + j;
        int tap = k / CIP, c = k - tap * CIP;
        float v = (n < DCH && c < 1080) ? sm[c * 9 + tap] : 0.f;
        g_Bgp[kc * (NPAD * 32) + n * 32 + j] = __float2bfloat16(v);
    }
}

// ------------------------------ MLP layer 1 --------------------------------
__global__ void layer1_kernel(const float* __restrict__ w1, const float* __restrict__ b1) {
    __shared__ float xs[30];
    int m = blockIdx.x; int tid = threadIdx.x;
    int n_img = m / PIX, pix = m - n_img * PIX;
    if (tid < 30) xs[tid] = g_epix[(n_img * 30 + tid) * PIX + pix];
    __syncthreads();
    float v = 0.f;
    if (tid < DCH) {
        v = b1[tid];
        #pragma unroll
        for (int c = 0; c < 30; c++) v += xs[c] * w1[tid * 30 + c];
        v = fmaxf(v, 0.f);
    }
    g_h[m * KPAD1 + tid] = __float2bfloat16(v);
}

// --------------------------- bf16 mma GEMM ---------------------------------
__device__ __forceinline__ void cp16(void* dst, const void* src) {
    unsigned s = (unsigned)__cvta_generic_to_shared(dst);
    asm volatile("cp.async.cg.shared.global [%0],[%1],16;\n" :: "r"(s), "l"(src));
}
__device__ __forceinline__ void ldsm4(uint32_t& r0, uint32_t& r1, uint32_t& r2, uint32_t& r3,
                                      const void* p) {
    unsigned a = (unsigned)__cvta_generic_to_shared(p);
    asm volatile("ldmatrix.sync.aligned.m8n8.x4.shared.b16 {%0,%1,%2,%3},[%4];\n"
                 : "=r"(r0), "=r"(r1), "=r"(r2), "=r"(r3) : "r"(a));
}

// MODE 0: m = tanh(h @ w2^T + b2)  (also writes m into g_gip)
// MODE 1: out = t_clip + sigmoid(conv + bg) * m   (implicit 3x3 conv GEMM)
template<int MODE>
__global__ __launch_bounds__(256) void mma_kernel(
    const float* __restrict__ bias, const float* __restrict__ t_clip,
    float* __restrict__ out, int ksteps)
{
    __shared__ __align__(16) __nv_bfloat16 As[3][128 * SB];
    __shared__ __align__(16) __nv_bfloat16 Bs[3][64 * SB];
    const __nv_bfloat16* Bp = (MODE == 0) ? g_B2p : g_Bgp;
    int tid = threadIdx.x, lane = tid & 31, w = tid >> 5;
    int wm = w >> 1, wn = w & 1;
    int bn = blockIdx.x, bm = blockIdx.y;

    // A stage load mapping: 128 rows x 32k; thread -> row=tid>>1, 2x16B chunks
    int arow = tid >> 1, ahalf = tid & 1;
    int m_glob = bm * 128 + arow;
    const __nv_bfloat16* a_base;
    if (MODE == 0) {
        a_base = g_h + m_glob * KPAD1 + ahalf * 16;
    } else {
        int n_img = m_glob / PIX, pix = m_glob - n_img * PIX;
        int y = pix / 14, x = pix - 14 * y;
        a_base = g_gip + ((n_img * 16 + y) * 16 + x) * CIP + ahalf * 16;
    }
    // B stage load mapping: 64 rows x 32k; thread -> row=tid>>2, 1x16B chunk
    int brow = tid >> 2, bq = tid & 3;
    const __nv_bfloat16* b_base = Bp + (bn * 64 + brow) * 32 + bq * 8;

    float acc[2][4][4];
    #pragma unroll
    for (int a = 0; a < 2; a++)
        #pragma unroll
        for (int q2 = 0; q2 < 4; q2++)
            #pragma unroll
            for (int c = 0; c < 4; c++) acc[a][q2][c] = 0.f;

    auto load = [&](int s, int kc) {
        __nv_bfloat16* ad = &As[s][arow * SB + ahalf * 16];
        if (MODE == 0) {
            const __nv_bfloat16* src = a_base + kc * 32;
            cp16(ad, src);
            cp16(ad + 8, src + 8);
        } else {
            int t9 = kc / 34, cc = (kc - t9 * 34) * 32;
            int ky = t9 / 3, kx = t9 - ky * 3;
            const __nv_bfloat16* src = a_base + (ky * 16 + kx) * CIP + cc;
            cp16(ad, src);
            cp16(ad + 8, src + 8);
        }
        cp16(&Bs[s][brow * SB + bq * 8], b_base + kc * (NPAD * 32));
        asm volatile("cp.async.commit_group;\n");
    };

    load(0, 0);
    load(1, 1);
    int g = lane >> 2, q = lane & 3;
    // ldmatrix source addresses (per-lane)
    int a_lrow = wm * 32 + (lane & 15);          // + mi*16
    int a_lcol = (lane >> 4) * 8;                // + sub*16
    int b_lrow = wn * 32 + (lane & 7) + ((lane >> 4) << 3);  // + pp*16
    int b_lcol = ((lane >> 3) & 1) * 8;          // + sub*16

    for (int kc = 0; kc < ksteps; kc++) {
        int s = kc % 3;
        if (kc + 2 < ksteps) { load((kc + 2) % 3, kc + 2); asm volatile("cp.async.wait_group 2;\n"); }
        else if (kc + 1 < ksteps) { asm volatile("cp.async.wait_group 1;\n"); }
        else { asm volatile("cp.async.wait_group 0;\n"); }
        __syncthreads();
        #pragma unroll
        for (int sub = 0; sub < 2; sub++) {
            uint32_t af[2][4], bf[4][2];
            #pragma unroll
            for (int mi = 0; mi < 2; mi++)
                ldsm4(af[mi][0], af[mi][1], af[mi][2], af[mi][3],
                      &As[s][(a_lrow + mi * 16) * SB + a_lcol + sub * 16]);
            #pragma unroll
            for (int pp = 0; pp < 2; pp++)
                ldsm4(bf[pp * 2][0], bf[pp * 2][1], bf[pp * 2 + 1][0], bf[pp * 2 + 1][1],
                      &Bs[s][(b_lrow + pp * 16) * SB + b_lcol + sub * 16]);
            #pragma unroll
            for (int mi = 0; mi < 2; mi++)
                #pragma unroll
                for (int ni = 0; ni < 4; ni++)
                    asm volatile("mma.sync.aligned.m16n8k16.row.col.f32.bf16.bf16.f32 "
                        "{%0,%1,%2,%3},{%4,%5,%6,%7},{%8,%9},{%0,%1,%2,%3};\n"
                        : "+f"(acc[mi][ni][0]), "+f"(acc[mi][ni][1]),
                          "+f"(acc[mi][ni][2]), "+f"(acc[mi][ni][3])
                        : "r"(af[mi][0]), "r"(af[mi][1]), "r"(af[mi][2]), "r"(af[mi][3]),
                          "r"(bf[ni][0]), "r"(bf[ni][1]));
        }
        __syncthreads();
    }

    // epilogue
    #pragma unroll
    for (int rr = 0; rr < 4; rr++) {
        int mi = rr >> 1, hh = rr & 1;
        int r = bm * 128 + wm * 32 + mi * 16 + g + hh * 8;
        int n_img = r / PIX, pix = r - n_img * PIX;
        int y = pix / 14, x = pix - 14 * y;
        int gbase = ((n_img * 16 + y + 1) * 16 + (x + 1)) * CIP + 540;
        #pragma unroll
        for (int ni = 0; ni < 4; ni++) {
            #pragma unroll
            for (int cc = 0; cc < 2; cc++) {
                int n = bn * 64 + wn * 32 + ni * 8 + 2 * q + cc;
                if (n >= DCH) continue;
                float v = acc[mi][ni][hh * 2 + cc] + bias[n];
                int oidx = (n_img * DCH + n) * PIX + pix;
                if (MODE == 0) {
                    v = tanhf(v);
                    g_m[oidx] = v;
                    g_gip[gbase + n] = __float2bfloat16(v);
                } else {
                    float gam = 1.f / (1.f + __expf(-v));
                    out[oidx] = t_clip[oidx] + gam * g_m[oidx];
                }
            }
        }
    }
}

// ------------------------------- launcher ----------------------------------
extern "C" void kernel_launch(void* const* d_in, const int* in_sizes, int n_in,
                              void* d_out, int out_size) {
    const float* frames = (const float*)d_in[0];
    const float* t_clip = (const float*)d_in[1];
    const float* w1 = (const float*)d_in[2];
    const float* b1 = (const float*)d_in[3];
    const float* w2 = (const float*)d_in[4];
    const float* b2 = (const float*)d_in[5];
    const float* wg = (const float*)d_in[6];
    const float* bg = (const float*)d_in[7];
    float* out = (float*)d_out;

    int tot = SLICES * HW;
    for (int l = 0; l < 3; l++) ca_kernel<<<(tot + 255) / 256, 256>>>(frames, l);

    cudaFuncSetAttribute(band_kernel, cudaFuncAttributeMaxDynamicSharedMemorySize, HW * 4);
    band_kernel<<<1920, 1024, HW * 4>>>(frames);

    zero_gi<<<(64 * 256 * CIP + 255) / 256, 256>>>();
    trans_gi<<<dim3(64, 34), 256>>>(t_clip);
    pack_w2<<<(17 * NPAD * 32 + 255) / 256, 256>>>(w2);
    pack_wg<<<NPAD, 256>>>(wg);
    layer1_kernel<<<M_TOT, 544>>>(w1, b1);

    mma_kernel<0><<<dim3(9, 98), 256>>>(b2, t_clip, out, 17);
    mma_kernel<1><<<dim3(9, 98), 256>>>(bg, t_clip, out, 306);
}